// round 9
// baseline (speedup 1.0000x reference)
#include <cuda_runtime.h>
#include <cuda_fp16.h>
#include <cuda_bf16.h>

// ---------------------------------------------------------------------------
// Problem constants
// ---------------------------------------------------------------------------
#define NXg 256
#define NBg 256
#define NK  64
#define LPE 4

static __device__ __constant__ float c_E2[8] = {
    4.0f/9.0f, 1.0f/9.0f, 1.0f/9.0f, 4.0f/9.0f,
    4.0f/9.0f, 1.0f/9.0f, 1.0f/9.0f, 4.0f/9.0f
};

#define LXMIN_D (-9.210340371976182)   /* log(1e-4) */
#define LBMIN_D (-6.907755278982137)   /* log(1e-3) */
#define LBMAX_D ( 3.912023005428146)   /* log(50)   */

// ---------------------------------------------------------------------------
// Device scratch (static — no allocation)
// Row-pair duplicated layout: cell (i,j) holds BOTH row i and row i+1:
//   [i][j][0][f] = grid[f][i][j],  [i][j][1][f] = grid[f][i+1][j]
// so the whole 2x2 bilinear stencil for (i, j0) is 64 contiguous bytes
// (columns j0 and j0+1 are adjacent cells).
// ---------------------------------------------------------------------------
__device__ __half g_pdf2[NXg * NBg * 16];   // 2 MB, E2 baked in
__device__ __half g_ff2 [NXg * NBg * 16];   // 2 MB
__device__ float  g_fnpc[3];
__device__ int    g_kmaxtab[128];           // conservative trip count buckets

__device__ __forceinline__ float4 lerp4(float4 a, float4 b, float t) {
    float4 r;
    r.x = fmaf(t, b.x - a.x, a.x);
    r.y = fmaf(t, b.y - a.y, a.y);
    r.z = fmaf(t, b.z - a.z, a.z);
    r.w = fmaf(t, b.w - a.w, a.w);
    return r;
}

__device__ __forceinline__ void h8_to_f(uint4 v, float4& a, float4& b) {
    const __half2* h = reinterpret_cast<const __half2*>(&v);
    float2 f0 = __half22float2(h[0]);
    float2 f1 = __half22float2(h[1]);
    float2 f2 = __half22float2(h[2]);
    float2 f3 = __half22float2(h[3]);
    a = make_float4(f0.x, f0.y, f1.x, f1.y);
    b = make_float4(f2.x, f2.y, f3.x, f3.y);
}

// ---------------------------------------------------------------------------
// Kernel 1: build row-pair-duplicated fp16 grids + fnp uniforms + kmax table.
// One thread per (i,j) cell; reads rows i and i+1 of all 8 flavors.
// ---------------------------------------------------------------------------
__global__ __launch_bounds__(256)
void prep_kernel(const float* __restrict__ pdf,
                 const float* __restrict__ ff,
                 const float* __restrict__ ogx,
                 const float* __restrict__ fnp)
{
    int ij = blockIdx.x * blockDim.x + threadIdx.x;

    if (ij == 0) {
        float p0 = fnp[0], p1 = fnp[1], p2 = fnp[2], p3 = fnp[3];
        float lam_p = log1pf(__expf(p0));
        float lam_f = log1pf(__expf(p1));
        float sig2  = __fdividef(1.0f, 1.0f + __expf(-p2));
        float sig3  = __fdividef(1.0f, 1.0f + __expf(-p3));
        g_fnpc[0] = lam_p;
        g_fnpc[1] = lam_p * sig2;
        g_fnpc[2] = lam_f * (1.0f + sig3);
    }

    // conservative trip-count buckets over U2 = u_max^2 threshold
    if (ij < 128) {
        int cnt;
        if (ij == 127) {
            cnt = NK;
        } else {
            float U2_hi = exp2f((float)(ij + 1) * 0.125f - 6.0f);
            cnt = 0;
            for (int k = 0; k < NK; k++) {
                float u = ogx[k];
                if (u * u <= U2_hi) cnt = k + 1;
            }
        }
        g_kmaxtab[ij] = cnt;
    }

    if (ij >= NXg * NBg) return;

    int i  = ij >> 8;            // row
    int j  = ij & 255;           // col
    int i1 = min(i + 1, NXg - 1);
    int base0 = i  * NBg + j;
    int base1 = i1 * NBg + j;

    union { uint4 u[2]; __half h[16]; } pk, fk;
#pragma unroll
    for (int f = 0; f < 8; f++) {
        pk.h[f]     = __float2half_rn(c_E2[f] * pdf[f * (NXg * NBg) + base0]);
        pk.h[f + 8] = __float2half_rn(c_E2[f] * pdf[f * (NXg * NBg) + base1]);
        fk.h[f]     = __float2half_rn(ff[f * (NXg * NBg) + base0]);
        fk.h[f + 8] = __float2half_rn(ff[f * (NXg * NBg) + base1]);
    }
    uint4* pd = reinterpret_cast<uint4*>(g_pdf2 + ij * 16);
    uint4* fd = reinterpret_cast<uint4*>(g_ff2  + ij * 16);
    pd[0] = pk.u[0];  pd[1] = pk.u[1];
    fd[0] = fk.u[0];  fd[1] = fk.u[1];
}

// ---------------------------------------------------------------------------
// Kernel 2: main — 4 lanes per event, bucket-table trip count.
// Each event-k now reads ONE 64B contiguous region per grid.
// ---------------------------------------------------------------------------
__global__ __launch_bounds__(256)
void sidis_kernel(const float* __restrict__ ev,
                  const float* __restrict__ ogx,
                  const float* __restrict__ ogw,
                  float* __restrict__ out,
                  int n_events)
{
    __shared__ float s_u2[NK], s_lu[NK], s_w[NK];
    __shared__ int   s_km[128];
    int t = threadIdx.x;
    if (t < NK) {
        float u = ogx[t];
        s_u2[t] = u * u;
        s_lu[t] = __logf(u);
        s_w[t]  = ogw[t];
    }
    if (t < 128) s_km[t] = g_kmaxtab[t];
    __syncthreads();

    int gt  = blockIdx.x * blockDim.x + t;
    int n   = gt >> 2;
    int sub = gt & 3;
    if (n >= n_events) return;

    const float LXMIN  = (float)LXMIN_D;
    const float LBMIN  = (float)LBMIN_D;
    const float XSCALE = (float)(255.0 / (0.0 - LXMIN_D));
    const float BSCALE = (float)(255.0 / (LBMAX_D - LBMIN_D));

    float4 e = __ldg(reinterpret_cast<const float4*>(ev) + n);
    float x = e.x, PhT = e.y, Q = e.z, z = e.w;

    float rz  = __fdividef(1.0f, z);
    float rP  = __fdividef(1.0f, PhT);
    float qT     = PhT * rz;
    float inv_qT = z * rP;
    float inv_z2 = rz * rz;
    float Q2  = Q * Q;

    float lx = __logf(x);
    float fx = fminf(fmaxf((lx - LXMIN) * XSCALE, 0.0f), 255.0f - 1e-4f);
    int   i0p = (int)fx;
    float txp = fx - (float)i0p;

    float lz = __logf(z);
    float fz = fminf(fmaxf((lz - LXMIN) * XSCALE, 0.0f), 255.0f - 1e-4f);
    int   i0f = (int)fz;
    float txf = fz - (float)i0f;

    float lQ2 = 2.0f * __logf(Q);
    float log_invqT = lz - __logf(PhT);

    float A = g_fnpc[0], B = g_fnpc[1], C = g_fnpc[2];
    float c = fmaf(0.12f, lQ2, A) - B * lx + C * inv_z2;
    float cq = c * inv_qT * inv_qT;           // arg_k = -cq * u_k^2

    float U2 = s_u2[0] + 36.0f * __fdividef(1.0f, cq);
    int bkt = (int)((__log2f(U2) + 6.0f) * 8.0f);
    bkt = min(max(bkt, 0), 127);
    int kmax = s_km[bkt];

    const __half* pbase = g_pdf2 + i0p * (NBg * 16);
    const __half* fbase = g_ff2  + i0f * (NBg * 16);

    float acc = 0.0f;
#pragma unroll 2
    for (int k = sub; k < kmax; k += LPE) {
        float arg = -cq * s_u2[k];

        float lb = s_lu[k] + log_invqT;
        float fb = fminf(fmaxf((lb - LBMIN) * BSCALE, 0.0f), 255.0f - 1e-4f);
        int   j0 = (int)fb;
        float tb = fb - (float)j0;

        // one 64B contiguous region per grid: [j0][{row0,row1}][8f], [j0+1][...]
        const uint4* pp = reinterpret_cast<const uint4*>(pbase + j0 * 16);
        uint4 P00 = __ldg(pp);      // row0 col j0
        uint4 P10 = __ldg(pp + 1);  // row1 col j0
        uint4 P01 = __ldg(pp + 2);  // row0 col j0+1
        uint4 P11 = __ldg(pp + 3);  // row1 col j0+1

        const uint4* fp = reinterpret_cast<const uint4*>(fbase + j0 * 16);
        uint4 F00 = __ldg(fp);
        uint4 F10 = __ldg(fp + 1);
        uint4 F01 = __ldg(fp + 2);
        uint4 F11 = __ldg(fp + 3);

        float4 pa0, pa1, pb0, pb1, pc0, pc1, pd0, pd1;
        h8_to_f(P00, pa0, pa1);  h8_to_f(P01, pb0, pb1);
        h8_to_f(P10, pc0, pc1);  h8_to_f(P11, pd0, pd1);

        float4 fa0, fa1, fb0, fb1, fc0, fc1, fd0, fd1;
        h8_to_f(F00, fa0, fa1);  h8_to_f(F01, fb0, fb1);
        h8_to_f(F10, fc0, fc1);  h8_to_f(F11, fd0, fd1);

        float4 pr0l = lerp4(pa0, pb0, tb);
        float4 pr0h = lerp4(pa1, pb1, tb);
        float4 pr1l = lerp4(pc0, pd0, tb);
        float4 pr1h = lerp4(pc1, pd1, tb);
        float4 pvl  = lerp4(pr0l, pr1l, txp);
        float4 pvh  = lerp4(pr0h, pr1h, txp);

        float4 fr0l = lerp4(fa0, fb0, tb);
        float4 fr0h = lerp4(fa1, fb1, tb);
        float4 fr1l = lerp4(fc0, fd0, tb);
        float4 fr1h = lerp4(fc1, fd1, tb);
        float4 fvl  = lerp4(fr0l, fr1l, txf);
        float4 fvh  = lerp4(fr0h, fr1h, txf);

        float s = pvl.x * fvl.x + pvl.y * fvl.y + pvl.z * fvl.z + pvl.w * fvl.w
                + pvh.x * fvh.x + pvh.y * fvh.y + pvh.z * fvh.z + pvh.w * fvh.w;

        acc = fmaf(s * s_w[k], __expf(arg), acc);
    }

    acc += __shfl_xor_sync(0xFFFFFFFFu, acc, 1);
    acc += __shfl_xor_sync(0xFFFFFFFFu, acc, 2);

    if (sub == 0) {
        float FUUT = acc * inv_qT * inv_qT;

        const float ALPHA0 = 0.00729735253f;
        const float L_ME2  = 15.1582899f;
        float rx = __fdividef(1.0f, x);
        float rQ = __fdividef(1.0f, Q);
        float lQme = lQ2 + L_ME2;
        float alpha = __fdividef(ALPHA0,
                      1.0f - (ALPHA0 / (3.0f * 3.14159265358979f)) * lQme);
        float gamma = 2.0f * 0.8803f * x * rQ;
        float y  = Q2 * rx * (1.0f / (140.0f - 0.8803f));
        float g2y2 = gamma * gamma * y * y;
        float epsn = 1.0f - y - 0.25f * g2y2;
        float epsd = 1.0f - y + 0.5f * y * y + 0.25f * g2y2;
        float eps  = __fdividef(epsn, epsd);
        float pre = 78.9568352f
                  * alpha * alpha * (z * z) * qT
                  * rx * (rQ * rQ * rQ)
                  * (y * y) * 0.5f * __fdividef(1.0f, 1.0f - eps)
                  * (1.0f + gamma * gamma * (0.5f * rx));

        out[n] = pre * FUUT;
    }
}

// ---------------------------------------------------------------------------
// kernel_launch
// Inputs: events (N,4), pdf (8,256,256), ff (8,256,256), ogata_x (64),
// ogata_w (64), fnp (4)
// ---------------------------------------------------------------------------
extern "C" void kernel_launch(void* const* d_in, const int* in_sizes, int n_in,
                              void* d_out, int out_size)
{
    const float* ev   = (const float*)d_in[0];
    const float* pdfg = (const float*)d_in[1];
    const float* ffg  = (const float*)d_in[2];
    const float* ogx  = (const float*)d_in[3];
    const float* ogw  = (const float*)d_in[4];
    const float* fnp  = (const float*)d_in[5];
    float* out = (float*)d_out;

    int n_events = in_sizes[0] / 4;

    prep_kernel<<<(NXg * NBg + 255) / 256, 256>>>(pdfg, ffg, ogx, fnp);

    int total_threads = n_events * LPE;
    int blocks = (total_threads + 255) / 256;
    sidis_kernel<<<blocks, 256>>>(ev, ogx, ogw, out, n_events);
}

// round 10
// speedup vs baseline: 1.1600x; 1.1600x over previous
#include <cuda_runtime.h>
#include <cuda_fp16.h>
#include <cuda_bf16.h>

// ---------------------------------------------------------------------------
// Problem constants
// ---------------------------------------------------------------------------
#define NXg 256
#define NBg 256
#define NK  64
#define LPE 4

static __device__ __constant__ float c_E2[8] = {
    4.0f/9.0f, 1.0f/9.0f, 1.0f/9.0f, 4.0f/9.0f,
    4.0f/9.0f, 1.0f/9.0f, 1.0f/9.0f, 4.0f/9.0f
};

#define LXMIN_D (-9.210340371976182)   /* log(1e-4) */
#define LBMIN_D (-6.907755278982137)   /* log(1e-3) */
#define LBMAX_D ( 3.912023005428146)   /* log(50)   */

// ---------------------------------------------------------------------------
// Device scratch (static — no allocation)
// Flat fp16 layout: [i][j][f], flavor innermost (16B per cell), E2 baked in.
// ---------------------------------------------------------------------------
__device__ __half g_pdf_h[NXg * NBg * 8];
__device__ __half g_ff_h [NXg * NBg * 8];
__device__ float  g_fnpc[3];

__device__ __forceinline__ float4 lerp4(float4 a, float4 b, float t) {
    float4 r;
    r.x = fmaf(t, b.x - a.x, a.x);
    r.y = fmaf(t, b.y - a.y, a.y);
    r.z = fmaf(t, b.z - a.z, a.z);
    r.w = fmaf(t, b.w - a.w, a.w);
    return r;
}

__device__ __forceinline__ void h8_to_f(uint4 v, float4& a, float4& b) {
    const __half2* h = reinterpret_cast<const __half2*>(&v);
    float2 f0 = __half22float2(h[0]);
    float2 f1 = __half22float2(h[1]);
    float2 f2 = __half22float2(h[2]);
    float2 f3 = __half22float2(h[3]);
    a = make_float4(f0.x, f0.y, f1.x, f1.y);
    b = make_float4(f2.x, f2.y, f3.x, f3.y);
}

// ---------------------------------------------------------------------------
// Kernel 1: transpose to fp16 [i][j][f]. 512 blocks: blocks [0,256) handle
// pdf (E2 baked in), blocks [256,512) handle ff — 2x the parallelism of the
// old single-pass version, halving this serial stage.
// ---------------------------------------------------------------------------
__global__ __launch_bounds__(256)
void prep_kernel(const float* __restrict__ pdf,
                 const float* __restrict__ ff,
                 const float* __restrict__ fnp)
{
    int b  = blockIdx.x;
    int t  = threadIdx.x;
    int ij = (b & 255) * 256 + t;          // cell index 0..65535
    bool do_pdf = (b < 256);

    if (b == 0 && t == 0) {
        float p0 = fnp[0], p1 = fnp[1], p2 = fnp[2], p3 = fnp[3];
        float lam_p = log1pf(__expf(p0));
        float lam_f = log1pf(__expf(p1));
        float sig2  = __fdividef(1.0f, 1.0f + __expf(-p2));
        float sig3  = __fdividef(1.0f, 1.0f + __expf(-p3));
        g_fnpc[0] = lam_p;
        g_fnpc[1] = lam_p * sig2;
        g_fnpc[2] = lam_f * (1.0f + sig3);
    }

    const float* src = do_pdf ? pdf : ff;
    __half*      dst = do_pdf ? g_pdf_h : g_ff_h;

    union { uint4 u; __half h[8]; } pk;
#pragma unroll
    for (int f = 0; f < 8; f++) {
        float v = src[f * (NXg * NBg) + ij];
        if (do_pdf) v *= c_E2[f];
        pk.h[f] = __float2half_rn(v);
    }
    reinterpret_cast<uint4*>(dst)[ij] = pk.u;
}

// ---------------------------------------------------------------------------
// Kernel 2: main — 4 lanes per event, straight-line single pass.
// Physics bound: cq >= ~1.3 -> U2 <= ~28 < u_5^2, so kmax <= 4 and each lane
// does at most ONE body execution (predicated). A rarely-taken tail loop
// guards correctness for pathological inputs.
// ---------------------------------------------------------------------------
__global__ __launch_bounds__(256)
void sidis_kernel(const float* __restrict__ ev,
                  const float* __restrict__ ogx,
                  const float* __restrict__ ogw,
                  float* __restrict__ out,
                  int n_events)
{
    __shared__ float s_u2[NK], s_lu[NK], s_w[NK];
    int t = threadIdx.x;
    if (t < NK) {
        float u = ogx[t];
        s_u2[t] = u * u;
        s_lu[t] = __logf(u);
        s_w[t]  = ogw[t];
    }
    __syncthreads();

    int gt  = blockIdx.x * blockDim.x + t;
    int n   = gt >> 2;
    int sub = gt & 3;
    if (n >= n_events) return;

    const float LXMIN  = (float)LXMIN_D;
    const float LBMIN  = (float)LBMIN_D;
    const float XSCALE = (float)(255.0 / (0.0 - LXMIN_D));
    const float BSCALE = (float)(255.0 / (LBMAX_D - LBMIN_D));

    float4 e = __ldg(reinterpret_cast<const float4*>(ev) + n);
    float x = e.x, PhT = e.y, Q = e.z, z = e.w;

    float rz  = __fdividef(1.0f, z);
    float rP  = __fdividef(1.0f, PhT);
    float qT     = PhT * rz;
    float inv_qT = z * rP;
    float inv_z2 = rz * rz;
    float Q2  = Q * Q;

    float lx = __logf(x);
    float fx = fminf(fmaxf((lx - LXMIN) * XSCALE, 0.0f), 255.0f - 1e-4f);
    int   i0p = (int)fx;
    float txp = fx - (float)i0p;

    float lz = __logf(z);
    float fz = fminf(fmaxf((lz - LXMIN) * XSCALE, 0.0f), 255.0f - 1e-4f);
    int   i0f = (int)fz;
    float txf = fz - (float)i0f;

    float lQ2 = 2.0f * __logf(Q);
    float log_invqT = lz - __logf(PhT);

    float A = g_fnpc[0], B = g_fnpc[1], C = g_fnpc[2];
    float c = fmaf(0.12f, lQ2, A) - B * lx + C * inv_z2;
    float cq = c * inv_qT * inv_qT;           // arg_k = -cq * u_k^2

    // inclusion threshold: keep k while cq*(u_k^2 - u_0^2) <= 36
    float U2 = s_u2[0] + 36.0f * __fdividef(1.0f, cq);

    const __half* pbase = g_pdf_h + i0p * (NBg * 8);
    const __half* fbase = g_ff_h  + i0f * (NBg * 8);

    float acc = 0.0f;

    // --- single predicated pass: k = sub ---
    if (s_u2[sub] <= U2) {
        int   k  = sub;
        float lb = s_lu[k] + log_invqT;
        float fb = fminf(fmaxf((lb - LBMIN) * BSCALE, 0.0f), 255.0f - 1e-4f);
        int   j0 = (int)fb;
        float tb = fb - (float)j0;

        const uint4* pr0 = reinterpret_cast<const uint4*>(pbase + j0 * 8);
        const uint4* pr1 = reinterpret_cast<const uint4*>(pbase + NBg * 8 + j0 * 8);
        uint4 P00 = __ldg(pr0), P01 = __ldg(pr0 + 1);
        uint4 P10 = __ldg(pr1), P11 = __ldg(pr1 + 1);

        const uint4* fr0 = reinterpret_cast<const uint4*>(fbase + j0 * 8);
        const uint4* fr1 = reinterpret_cast<const uint4*>(fbase + NBg * 8 + j0 * 8);
        uint4 F00 = __ldg(fr0), F01 = __ldg(fr0 + 1);
        uint4 F10 = __ldg(fr1), F11 = __ldg(fr1 + 1);

        float4 pa0, pa1, pb0, pb1, pc0, pc1, pd0, pd1;
        h8_to_f(P00, pa0, pa1);  h8_to_f(P01, pb0, pb1);
        h8_to_f(P10, pc0, pc1);  h8_to_f(P11, pd0, pd1);

        float4 fa0, fa1, fb0, fb1, fc0, fc1, fd0, fd1;
        h8_to_f(F00, fa0, fa1);  h8_to_f(F01, fb0, fb1);
        h8_to_f(F10, fc0, fc1);  h8_to_f(F11, fd0, fd1);

        float4 pr0l = lerp4(pa0, pb0, tb);
        float4 pr0h = lerp4(pa1, pb1, tb);
        float4 pr1l = lerp4(pc0, pd0, tb);
        float4 pr1h = lerp4(pc1, pd1, tb);
        float4 pvl  = lerp4(pr0l, pr1l, txp);
        float4 pvh  = lerp4(pr0h, pr1h, txp);

        float4 fr0l = lerp4(fa0, fb0, tb);
        float4 fr0h = lerp4(fa1, fb1, tb);
        float4 fr1l = lerp4(fc0, fd0, tb);
        float4 fr1h = lerp4(fc1, fd1, tb);
        float4 fvl  = lerp4(fr0l, fr1l, txf);
        float4 fvh  = lerp4(fr0h, fr1h, txf);

        float s = pvl.x * fvl.x + pvl.y * fvl.y + pvl.z * fvl.z + pvl.w * fvl.w
                + pvh.x * fvh.x + pvh.y * fvh.y + pvh.z * fvh.z + pvh.w * fvh.w;

        acc = s * s_w[k] * __expf(-cq * s_u2[k]);
    }

    // --- rare tail (kmax > 4): almost never executes ---
    for (int k = sub + LPE; k < NK && s_u2[k] <= U2; k += LPE) {
        float lb = s_lu[k] + log_invqT;
        float fb = fminf(fmaxf((lb - LBMIN) * BSCALE, 0.0f), 255.0f - 1e-4f);
        int   j0 = (int)fb;
        float tb = fb - (float)j0;

        const uint4* pr0 = reinterpret_cast<const uint4*>(pbase + j0 * 8);
        const uint4* pr1 = reinterpret_cast<const uint4*>(pbase + NBg * 8 + j0 * 8);
        uint4 P00 = __ldg(pr0), P01 = __ldg(pr0 + 1);
        uint4 P10 = __ldg(pr1), P11 = __ldg(pr1 + 1);

        const uint4* fr0 = reinterpret_cast<const uint4*>(fbase + j0 * 8);
        const uint4* fr1 = reinterpret_cast<const uint4*>(fbase + NBg * 8 + j0 * 8);
        uint4 F00 = __ldg(fr0), F01 = __ldg(fr0 + 1);
        uint4 F10 = __ldg(fr1), F11 = __ldg(fr1 + 1);

        float4 pa0, pa1, pb0, pb1, pc0, pc1, pd0, pd1;
        h8_to_f(P00, pa0, pa1);  h8_to_f(P01, pb0, pb1);
        h8_to_f(P10, pc0, pc1);  h8_to_f(P11, pd0, pd1);

        float4 fa0, fa1, fb0, fb1, fc0, fc1, fd0, fd1;
        h8_to_f(F00, fa0, fa1);  h8_to_f(F01, fb0, fb1);
        h8_to_f(F10, fc0, fc1);  h8_to_f(F11, fd0, fd1);

        float4 pr0l = lerp4(pa0, pb0, tb);
        float4 pr0h = lerp4(pa1, pb1, tb);
        float4 pr1l = lerp4(pc0, pd0, tb);
        float4 pr1h = lerp4(pc1, pd1, tb);
        float4 pvl  = lerp4(pr0l, pr1l, txp);
        float4 pvh  = lerp4(pr0h, pr1h, txp);

        float4 fr0l = lerp4(fa0, fb0, tb);
        float4 fr0h = lerp4(fa1, fb1, tb);
        float4 fr1l = lerp4(fc0, fd0, tb);
        float4 fr1h = lerp4(fc1, fd1, tb);
        float4 fvl  = lerp4(fr0l, fr1l, txf);
        float4 fvh  = lerp4(fr0h, fr1h, txf);

        float s = pvl.x * fvl.x + pvl.y * fvl.y + pvl.z * fvl.z + pvl.w * fvl.w
                + pvh.x * fvh.x + pvh.y * fvh.y + pvh.z * fvh.z + pvh.w * fvh.w;

        acc = fmaf(s * s_w[k], __expf(-cq * s_u2[k]), acc);
    }

    acc += __shfl_xor_sync(0xFFFFFFFFu, acc, 1);
    acc += __shfl_xor_sync(0xFFFFFFFFu, acc, 2);

    if (sub == 0) {
        float FUUT = acc * inv_qT * inv_qT;

        const float ALPHA0 = 0.00729735253f;
        const float L_ME2  = 15.1582899f;
        float rx = __fdividef(1.0f, x);
        float rQ = __fdividef(1.0f, Q);
        float lQme = lQ2 + L_ME2;
        float alpha = __fdividef(ALPHA0,
                      1.0f - (ALPHA0 / (3.0f * 3.14159265358979f)) * lQme);
        float gamma = 2.0f * 0.8803f * x * rQ;
        float y  = Q2 * rx * (1.0f / (140.0f - 0.8803f));
        float g2y2 = gamma * gamma * y * y;
        float epsn = 1.0f - y - 0.25f * g2y2;
        float epsd = 1.0f - y + 0.5f * y * y + 0.25f * g2y2;
        float eps  = __fdividef(epsn, epsd);
        float pre = 78.9568352f
                  * alpha * alpha * (z * z) * qT
                  * rx * (rQ * rQ * rQ)
                  * (y * y) * 0.5f * __fdividef(1.0f, 1.0f - eps)
                  * (1.0f + gamma * gamma * (0.5f * rx));

        out[n] = pre * FUUT;
    }
}

// ---------------------------------------------------------------------------
// kernel_launch
// Inputs: events (N,4), pdf (8,256,256), ff (8,256,256), ogata_x (64),
// ogata_w (64), fnp (4)
// ---------------------------------------------------------------------------
extern "C" void kernel_launch(void* const* d_in, const int* in_sizes, int n_in,
                              void* d_out, int out_size)
{
    const float* ev   = (const float*)d_in[0];
    const float* pdfg = (const float*)d_in[1];
    const float* ffg  = (const float*)d_in[2];
    const float* ogx  = (const float*)d_in[3];
    const float* ogw  = (const float*)d_in[4];
    const float* fnp  = (const float*)d_in[5];
    float* out = (float*)d_out;

    int n_events = in_sizes[0] / 4;

    prep_kernel<<<512, 256>>>(pdfg, ffg, fnp);

    int total_threads = n_events * LPE;
    int blocks = (total_threads + 255) / 256;
    sidis_kernel<<<blocks, 256>>>(ev, ogx, ogw, out, n_events);
}

// round 11
// speedup vs baseline: 1.1897x; 1.0256x over previous
#include <cuda_runtime.h>
#include <cuda_fp16.h>
#include <cuda_bf16.h>

// ---------------------------------------------------------------------------
// Problem constants
// ---------------------------------------------------------------------------
#define NXg 256
#define NBg 256
#define NK  64
#define LPE 4

static __device__ __constant__ float c_E2[8] = {
    4.0f/9.0f, 1.0f/9.0f, 1.0f/9.0f, 4.0f/9.0f,
    4.0f/9.0f, 1.0f/9.0f, 1.0f/9.0f, 4.0f/9.0f
};

#define LXMIN_D (-9.210340371976182)   /* log(1e-4) */
#define LBMIN_D (-6.907755278982137)   /* log(1e-3) */
#define LBMAX_D ( 3.912023005428146)   /* log(50)   */

// ---------------------------------------------------------------------------
// Device scratch (static — no allocation)
// Flat fp16 layout: [i][j][f], flavor innermost (16B per cell), E2 baked in.
// ---------------------------------------------------------------------------
__device__ __half g_pdf_h[NXg * NBg * 8];
__device__ __half g_ff_h [NXg * NBg * 8];
__device__ float  g_fnpc[3];

// ---------------------------------------------------------------------------
// Kernel 1: transpose to fp16 [i][j][f]. 512 blocks: [0,256) pdf (E2 baked),
// [256,512) ff.
// ---------------------------------------------------------------------------
__global__ __launch_bounds__(256)
void prep_kernel(const float* __restrict__ pdf,
                 const float* __restrict__ ff,
                 const float* __restrict__ fnp)
{
    int b  = blockIdx.x;
    int t  = threadIdx.x;
    int ij = (b & 255) * 256 + t;
    bool do_pdf = (b < 256);

    if (b == 0 && t == 0) {
        float p0 = fnp[0], p1 = fnp[1], p2 = fnp[2], p3 = fnp[3];
        float lam_p = log1pf(__expf(p0));
        float lam_f = log1pf(__expf(p1));
        float sig2  = __fdividef(1.0f, 1.0f + __expf(-p2));
        float sig3  = __fdividef(1.0f, 1.0f + __expf(-p3));
        g_fnpc[0] = lam_p;
        g_fnpc[1] = lam_p * sig2;
        g_fnpc[2] = lam_f * (1.0f + sig3);
    }

    const float* src = do_pdf ? pdf : ff;
    __half*      dst = do_pdf ? g_pdf_h : g_ff_h;

    union { uint4 u; __half h[8]; } pk;
#pragma unroll
    for (int f = 0; f < 8; f++) {
        float v = src[f * (NXg * NBg) + ij];
        if (do_pdf) v *= c_E2[f];
        pk.h[f] = __float2half_rn(v);
    }
    reinterpret_cast<uint4*>(dst)[ij] = pk.u;
}

// ---------------------------------------------------------------------------
// half2 bilinear: corners (row0col0, row0col1, row1col0, row1col1), each a
// uint4 = 4 half2 (8 flavors). Two lerp levels in half2 (HFMA2).
// ---------------------------------------------------------------------------
__device__ __forceinline__ void bilerp8_h2(uint4 A0, uint4 A1, uint4 B0, uint4 B1,
                                           __half2 tb, __half2 tx, __half2* out)
{
    const __half2* a0 = reinterpret_cast<const __half2*>(&A0);
    const __half2* a1 = reinterpret_cast<const __half2*>(&A1);
    const __half2* b0 = reinterpret_cast<const __half2*>(&B0);
    const __half2* b1 = reinterpret_cast<const __half2*>(&B1);
#pragma unroll
    for (int q = 0; q < 4; q++) {
        __half2 r0 = __hfma2(tb, __hsub2(a1[q], a0[q]), a0[q]);
        __half2 r1 = __hfma2(tb, __hsub2(b1[q], b0[q]), b0[q]);
        out[q] = __hfma2(tx, __hsub2(r1, r0), r0);
    }
}

// Per-k contribution: address math, 8 gathers, half2 bilerps, fp32 dot + exp.
__device__ __forceinline__ float kbody(int k, float cq, float log_invqT,
                                       __half2 txp2, __half2 txf2,
                                       const __half* pbase, const __half* fbase,
                                       const float* s_lu, const float* s_u2,
                                       const float* s_w)
{
    const float LBMIN  = (float)LBMIN_D;
    const float BSCALE = (float)(255.0 / (LBMAX_D - LBMIN_D));

    float lb = s_lu[k] + log_invqT;
    float fb = fminf(fmaxf((lb - LBMIN) * BSCALE, 0.0f), 255.0f - 1e-4f);
    int   j0 = (int)fb;
    float tb = fb - (float)j0;
    __half2 tb2 = __float2half2_rn(tb);

    const uint4* pr0 = reinterpret_cast<const uint4*>(pbase + j0 * 8);
    const uint4* pr1 = reinterpret_cast<const uint4*>(pbase + NBg * 8 + j0 * 8);
    uint4 P00 = __ldg(pr0), P01 = __ldg(pr0 + 1);
    uint4 P10 = __ldg(pr1), P11 = __ldg(pr1 + 1);

    const uint4* fr0 = reinterpret_cast<const uint4*>(fbase + j0 * 8);
    const uint4* fr1 = reinterpret_cast<const uint4*>(fbase + NBg * 8 + j0 * 8);
    uint4 F00 = __ldg(fr0), F01 = __ldg(fr0 + 1);
    uint4 F10 = __ldg(fr1), F11 = __ldg(fr1 + 1);

    __half2 pv[4], fv[4];
    bilerp8_h2(P00, P01, P10, P11, tb2, txp2, pv);
    bilerp8_h2(F00, F01, F10, F11, tb2, txf2, fv);

    float s = 0.0f;
#pragma unroll
    for (int q = 0; q < 4; q++) {
        float2 a = __half22float2(pv[q]);
        float2 b = __half22float2(fv[q]);
        s = fmaf(a.x, b.x, s);
        s = fmaf(a.y, b.y, s);
    }
    return s * s_w[k] * __expf(-cq * s_u2[k]);
}

// ---------------------------------------------------------------------------
// Kernel 2: main — 4 lanes per event, straight-line predicated single pass
// (kmax <= 4 in practice), rare tail loop for safety. 6 CTAs/SM target.
// ---------------------------------------------------------------------------
__global__ __launch_bounds__(256, 6)
void sidis_kernel(const float* __restrict__ ev,
                  const float* __restrict__ ogx,
                  const float* __restrict__ ogw,
                  float* __restrict__ out,
                  int n_events)
{
    __shared__ float s_u2[NK], s_lu[NK], s_w[NK];
    int t = threadIdx.x;
    if (t < NK) {
        float u = ogx[t];
        s_u2[t] = u * u;
        s_lu[t] = __logf(u);
        s_w[t]  = ogw[t];
    }
    __syncthreads();

    int gt  = blockIdx.x * blockDim.x + t;
    int n   = gt >> 2;
    int sub = gt & 3;
    if (n >= n_events) return;

    const float LXMIN  = (float)LXMIN_D;
    const float XSCALE = (float)(255.0 / (0.0 - LXMIN_D));

    float4 e = __ldg(reinterpret_cast<const float4*>(ev) + n);
    float x = e.x, PhT = e.y, Q = e.z, z = e.w;

    float rz  = __fdividef(1.0f, z);
    float rP  = __fdividef(1.0f, PhT);
    float qT     = PhT * rz;
    float inv_qT = z * rP;
    float inv_z2 = rz * rz;
    float Q2  = Q * Q;

    float lx = __logf(x);
    float fx = fminf(fmaxf((lx - LXMIN) * XSCALE, 0.0f), 255.0f - 1e-4f);
    int   i0p = (int)fx;
    float txp = fx - (float)i0p;

    float lz = __logf(z);
    float fz = fminf(fmaxf((lz - LXMIN) * XSCALE, 0.0f), 255.0f - 1e-4f);
    int   i0f = (int)fz;
    float txf = fz - (float)i0f;

    float lQ2 = 2.0f * __logf(Q);
    float log_invqT = lz - __logf(PhT);

    float A = g_fnpc[0], B = g_fnpc[1], C = g_fnpc[2];
    float c = fmaf(0.12f, lQ2, A) - B * lx + C * inv_z2;
    float cq = c * inv_qT * inv_qT;           // arg_k = -cq * u_k^2

    float U2 = s_u2[0] + 36.0f * __fdividef(1.0f, cq);

    // ---- prefactor hoisted: overlaps its divide/MUFU latency with gathers
    const float ALPHA0 = 0.00729735253f;
    const float L_ME2  = 15.1582899f;
    float rx = __fdividef(1.0f, x);
    float rQ = __fdividef(1.0f, Q);
    float lQme = lQ2 + L_ME2;
    float alpha = __fdividef(ALPHA0,
                  1.0f - (ALPHA0 / (3.0f * 3.14159265358979f)) * lQme);
    float gamma = 2.0f * 0.8803f * x * rQ;
    float y  = Q2 * rx * (1.0f / (140.0f - 0.8803f));
    float g2y2 = gamma * gamma * y * y;
    float epsn = 1.0f - y - 0.25f * g2y2;
    float epsd = 1.0f - y + 0.5f * y * y + 0.25f * g2y2;
    float eps  = __fdividef(epsn, epsd);
    float pre = 78.9568352f
              * alpha * alpha * (z * z) * qT
              * rx * (rQ * rQ * rQ)
              * (y * y) * 0.5f * __fdividef(1.0f, 1.0f - eps)
              * (1.0f + gamma * gamma * (0.5f * rx))
              * (inv_qT * inv_qT);            // fold in FUUT's 1/qT^2

    __half2 txp2 = __float2half2_rn(txp);
    __half2 txf2 = __float2half2_rn(txf);

    const __half* pbase = g_pdf_h + i0p * (NBg * 8);
    const __half* fbase = g_ff_h  + i0f * (NBg * 8);

    float acc = 0.0f;

    // single predicated pass: k = sub (kmax <= 4 in practice)
    if (s_u2[sub] <= U2) {
        acc = kbody(sub, cq, log_invqT, txp2, txf2, pbase, fbase,
                    s_lu, s_u2, s_w);
    }
    // rare tail
    for (int k = sub + LPE; k < NK && s_u2[k] <= U2; k += LPE) {
        acc += kbody(k, cq, log_invqT, txp2, txf2, pbase, fbase,
                     s_lu, s_u2, s_w);
    }

    acc += __shfl_xor_sync(0xFFFFFFFFu, acc, 1);
    acc += __shfl_xor_sync(0xFFFFFFFFu, acc, 2);

    if (sub == 0) {
        out[n] = pre * acc;
    }
}

// ---------------------------------------------------------------------------
// kernel_launch
// Inputs: events (N,4), pdf (8,256,256), ff (8,256,256), ogata_x (64),
// ogata_w (64), fnp (4)
// ---------------------------------------------------------------------------
extern "C" void kernel_launch(void* const* d_in, const int* in_sizes, int n_in,
                              void* d_out, int out_size)
{
    const float* ev   = (const float*)d_in[0];
    const float* pdfg = (const float*)d_in[1];
    const float* ffg  = (const float*)d_in[2];
    const float* ogx  = (const float*)d_in[3];
    const float* ogw  = (const float*)d_in[4];
    const float* fnp  = (const float*)d_in[5];
    float* out = (float*)d_out;

    int n_events = in_sizes[0] / 4;

    prep_kernel<<<512, 256>>>(pdfg, ffg, fnp);

    int total_threads = n_events * LPE;
    int blocks = (total_threads + 255) / 256;
    sidis_kernel<<<blocks, 256>>>(ev, ogx, ogw, out, n_events);
}